// round 12
// baseline (speedup 1.0000x reference)
#include <cuda_runtime.h>
#include <math.h>

#define NB 32768
#define PITCH 65
#define NSUB (NB / 128)

typedef unsigned long long ull;

__device__ __forceinline__ ull ffma2(ull a, ull b, ull c) {
    ull d; asm("fma.rn.f32x2 %0, %1, %2, %3;" : "=l"(d) : "l"(a), "l"(b), "l"(c)); return d;
}
__device__ __forceinline__ ull pack2(float lo, float hi) {
    ull d; asm("mov.b64 %0, {%1, %2};" : "=l"(d) : "f"(lo), "f"(hi)); return d;
}
__device__ __forceinline__ void unpack2(ull v, float& lo, float& hi) {
    asm("mov.b64 {%0, %1}, %2;" : "=f"(lo), "=f"(hi) : "l"(v));
}

// scratch: [0..3]*NB = v00,v01,fV,V  (lyap -> barrier handoff)
__device__ float g_scr[4 * NB];
__device__ int g_flag[NSUB];   // zero-init; set by lyap, consumed+reset by barrier

// ---- forward 64x64 matvec: smem input, acc[q] covers outputs {2q,2q+1} ----
__device__ __forceinline__ void matvec64(const float* __restrict__ sWc,
                                         const float* __restrict__ tin, ull acc[32]) {
    #pragma unroll 4
    for (int k = 0; k < 64; k++) {
        float tk = tin[k];
        ull td = pack2(tk, tk);
        const ulonglong2* wp = (const ulonglong2*)(sWc + (k << 6));
        #pragma unroll
        for (int q = 0; q < 16; q++) {
            ulonglong2 w = wp[q];
            acc[2 * q]     = ffma2(w.x, td, acc[2 * q]);
            acc[2 * q + 1] = ffma2(w.y, td, acc[2 * q + 1]);
        }
    }
}

// ---- transposed matvec, register-array input, kt loop rolled.
//      EPI may only use dynamic-index-safe state (smem / scalars). ----
template <typename GET, typename EPI>
__device__ __forceinline__ void matvecT64_rolled(const float* __restrict__ sWc,
                                                 GET get, EPI epi) {
    #pragma unroll 1
    for (int kt = 0; kt < 4; kt++) {
        ull cacc[16];
        #pragma unroll
        for (int i = 0; i < 16; i++) cacc[i] = 0ull;
        #pragma unroll
        for (int q = 0; q < 16; q++) {
            ull a01 = pack2(get(4 * q), get(4 * q + 1));
            ull a23 = pack2(get(4 * q + 2), get(4 * q + 3));
            #pragma unroll
            for (int i = 0; i < 16; i++) {
                const ulonglong2* wp = (const ulonglong2*)(sWc + (((kt << 4) + i) << 6));
                ulonglong2 w = wp[q];
                cacc[i] = ffma2(w.x, a01, cacc[i]);
                cacc[i] = ffma2(w.y, a23, cacc[i]);
            }
        }
        #pragma unroll
        for (int i = 0; i < 16; i++) {
            float lo, hi; unpack2(cacc[i], lo, hi);
            epi((kt << 4) + i, lo + hi);
        }
    }
}

// ---- transposed matvec, FULLY unrolled (EPI may index register arrays) ----
template <typename GET, typename EPI>
__device__ __forceinline__ void matvecT64_full(const float* __restrict__ sWc,
                                               GET get, EPI epi) {
    #pragma unroll
    for (int kt = 0; kt < 4; kt++) {
        ull cacc[16];
        #pragma unroll
        for (int i = 0; i < 16; i++) cacc[i] = 0ull;
        #pragma unroll
        for (int q = 0; q < 16; q++) {
            ull a01 = pack2(get(4 * q), get(4 * q + 1));
            ull a23 = pack2(get(4 * q + 2), get(4 * q + 3));
            #pragma unroll
            for (int i = 0; i < 16; i++) {
                const ulonglong2* wp = (const ulonglong2*)(sWc + (((kt << 4) + i) << 6));
                ulonglong2 w = wp[q];
                cacc[i] = ffma2(w.x, a01, cacc[i]);
                cacc[i] = ffma2(w.y, a23, cacc[i]);
            }
        }
        #pragma unroll
        for (int i = 0; i < 16; i++) {
            float lo, hi; unpack2(cacc[i], lo, hi);
            epi((kt << 4) + i, lo + hi);
        }
    }
}

// ---- layer 1 (8 -> 64) + tanh -> smem column ----
__device__ __forceinline__ void layer1_smem(const float* __restrict__ sW1c,
                                            const float* __restrict__ sb1,
                                            const float xv[8], float* __restrict__ out) {
    ull acc[32];
    #pragma unroll
    for (int q = 0; q < 32; q++) acc[q] = 0ull;
    #pragma unroll
    for (int n = 0; n < 8; n++) {
        ull xd = pack2(xv[n], xv[n]);
        const ulonglong2* wp = (const ulonglong2*)(sW1c + (n << 6));
        #pragma unroll
        for (int q = 0; q < 16; q++) {
            ulonglong2 w = wp[q];
            acc[2 * q]     = ffma2(w.x, xd, acc[2 * q]);
            acc[2 * q + 1] = ffma2(w.y, xd, acc[2 * q + 1]);
        }
    }
    #pragma unroll
    for (int q = 0; q < 32; q++) {
        float lo, hi; unpack2(acc[q], lo, hi);
        float2 b = ((const float2*)sb1)[q];
        out[2 * q]     = tanhf(lo + b.x);
        out[2 * q + 1] = tanhf(hi + b.y);
    }
}

// ---- layer 1 -> register array ----
__device__ __forceinline__ void layer1_regs(const float* __restrict__ sW1c,
                                            const float* __restrict__ sb1,
                                            const float xv[8], float t1r[64]) {
    ull acc[32];
    #pragma unroll
    for (int q = 0; q < 32; q++) acc[q] = 0ull;
    #pragma unroll
    for (int n = 0; n < 8; n++) {
        ull xd = pack2(xv[n], xv[n]);
        const ulonglong2* wp = (const ulonglong2*)(sW1c + (n << 6));
        #pragma unroll
        for (int q = 0; q < 16; q++) {
            ulonglong2 w = wp[q];
            acc[2 * q]     = ffma2(w.x, xd, acc[2 * q]);
            acc[2 * q + 1] = ffma2(w.y, xd, acc[2 * q + 1]);
        }
    }
    #pragma unroll
    for (int q = 0; q < 32; q++) {
        float lo, hi; unpack2(acc[q], lo, hi);
        float2 b = ((const float2*)sb1)[q];
        t1r[2 * q]     = tanhf(lo + b.x);
        t1r[2 * q + 1] = tanhf(hi + b.y);
    }
}

// ===========================================================================
// Single fused kernel.
//   even blocks (role 0): Lyapunov MLP -> g_scr + flag release
//   odd  blocks (role 1): Barrier MLP (h-quad stays in regs) -> wait flag ->
//                         80-iter ADMM (analytic Schur inverse) -> outputs
// ===========================================================================
#define MLP_SMEM_FLOATS (128 * PITCH + 2 * 4096 + 512 + 512 + 128 + 4 * 64 + 16)
#define MLP_SMEM_BYTES (MLP_SMEM_FLOATS * 4)

extern "C" __global__ void __launch_bounds__(128, 3) mlp_kernel(
    const float* __restrict__ x,
    const float* __restrict__ VW1, const float* __restrict__ Vb1,
    const float* __restrict__ VW2, const float* __restrict__ Vb2,
    const float* __restrict__ HW1, const float* __restrict__ Hb1,
    const float* __restrict__ HW2, const float* __restrict__ Hb2,
    const float* __restrict__ HW3, const float* __restrict__ Hb3,
    const float* __restrict__ HW4, const float* __restrict__ Hb4,
    const float* __restrict__ G0, const float* __restrict__ K,
    float* __restrict__ out)
{
    extern __shared__ float sm[];
    float* scrA = sm;                      // 128*PITCH (one column / element)
    float* sWa  = scrA + 128 * PITCH;      // 4096: W2 col-major [k][j]
    float* sWb  = sWa + 4096;              // 4096: W3 col-major (barrier only)
    float* sW1c = sWb + 4096;              // 512  [n][j]
    float* sW1r = sW1c + 512;              // 512  row-major
    float* sW1G = sW1r + 512;              // 128  [k] pairs (g0,g1)
    float* sb1  = sW1G + 128;              // 64
    float* sb2  = sb1 + 64;                // 64
    float* sb3  = sb2 + 64;                // 64
    float* sW4  = sb3 + 64;                // 64
    float* sK   = sW4 + 64;                // 16

    const int tid  = threadIdx.x;
    const int role = blockIdx.x & 1;       // 0 = lyap, 1 = barrier+admm
    const int sub  = blockIdx.x >> 1;

    const float* W1 = role ? HW1 : VW1;
    const float* B1 = role ? Hb1 : Vb1;
    const float* W2 = role ? HW2 : VW2;
    const float* B2 = role ? Hb2 : Vb2;

    for (int i = tid; i < 4096; i += 128) {
        int j = i >> 6, k = i & 63;
        sWa[k * 64 + j] = W2[i];
        if (role) sWb[k * 64 + j] = HW3[i];
    }
    for (int i = tid; i < 512; i += 128) {
        int j = i >> 3, n = i & 7;
        sW1c[n * 64 + j] = W1[i];
        sW1r[i] = W1[i];
    }
    if (tid < 64) {
        sb1[tid] = B1[tid]; sb2[tid] = B2[tid];
        if (role) { sb3[tid] = Hb3[tid]; sW4[tid] = HW4[tid]; }
        float g0 = 0.f, g1 = 0.f;
        for (int n = 0; n < 8; n++) {
            float w = W1[tid * 8 + n];
            g0 = fmaf(w, G0[2 * n], g0);
            g1 = fmaf(w, G0[2 * n + 1], g1);
        }
        sW1G[2 * tid] = g0; sW1G[2 * tid + 1] = g1;
    }
    if (tid < 16) sK[tid] = K[tid];
    __syncthreads();

    const int elt = sub * 128 + tid;
    float4 xlo = ((const float4*)x)[elt * 2];
    float4 xhi = ((const float4*)x)[elt * 2 + 1];
    float xv[8] = {xlo.x, xlo.y, xlo.z, xlo.w, xhi.x, xhi.y, xhi.z, xhi.w};
    float* myA = scrA + tid * PITCH;

    // scalar accumulators for the final backward-through-W1 contraction
    ull hv = 0ull, gn0 = 0ull, gn1 = 0ull, gn2 = 0ull, gn3 = 0ull;

    if (role == 0) {
        // ================= Lyapunov =================
        layer1_smem(sW1c, sb1, xv, myA);   // t1 -> A (persists)

        ull acc[32];
        #pragma unroll
        for (int q = 0; q < 32; q++) acc[q] = 0ull;
        matvec64(sWa, myA, acc);           // layer-2 pre-activation

        float V = 0.f;
        float a2[64];                      // a2 = t2*(1-t2^2) in REGISTERS
        #pragma unroll
        for (int q = 0; q < 32; q++) {
            float lo, hi; unpack2(acc[q], lo, hi);
            float2 b = ((const float2*)sb2)[q];
            float t0 = tanhf(lo + b.x), t1v = tanhf(hi + b.y);
            V += t0 * t0 + t1v * t1v;
            a2[2 * q]     = t0 * (1.f - t0 * t0);
            a2[2 * q + 1] = t1v * (1.f - t1v * t1v);
        }
        V *= 0.5f;

        // backward through W2: epi reads t1 from smem (dynamic k safe)
        matvecT64_rolled(sWa,
            [&](int j) { return a2[j]; },
            [&](int k, float c) {
                float t1k = myA[k];
                float cc = c * (1.f - t1k * t1k);
                ull ccd = pack2(cc, cc);
                hv = ffma2(((const ull*)sW1G)[k], ccd, hv);
                const ulonglong2* wp = (const ulonglong2*)(sW1r + k * 8);
                ulonglong2 wa = wp[0], wb = wp[1];
                gn0 = ffma2(wa.x, ccd, gn0); gn1 = ffma2(wa.y, ccd, gn1);
                gn2 = ffma2(wb.x, ccd, gn2); gn3 = ffma2(wb.y, ccd, gn3);
            });

        float p0, p1; unpack2(hv, p0, p1);
        float g0, g1, g2, g3, g4, g5, g6, g7;
        unpack2(gn0, g0, g1); unpack2(gn1, g2, g3); unpack2(gn2, g4, g5); unpack2(gn3, g6, g7);
        float fV = -(g0 * xv[0] + g1 * xv[1] + g2 * xv[2] + g3 * xv[3] +
                     g4 * xv[4] + g5 * xv[5] + g6 * xv[6] + g7 * xv[7]);
        g_scr[0 * NB + elt] = p0;
        g_scr[1 * NB + elt] = p1;
        g_scr[2 * NB + elt] = fV;
        g_scr[3 * NB + elt] = V;

        // release: data visible device-wide, then set flag
        __threadfence();
        __syncthreads();
        if (tid == 0) atomicExch(&g_flag[sub], 1);
    } else {
        // ================= Barrier =================
        layer1_smem(sW1c, sb1, xv, myA);   // t1 -> A (temporary)

        ull acc[32];
        #pragma unroll
        for (int q = 0; q < 32; q++) acc[q] = 0ull;
        matvec64(sWa, myA, acc);           // layer 2 (consumes all of t1)
        #pragma unroll
        for (int q = 0; q < 32; q++) {     // t2 overwrites A
            float lo, hi; unpack2(acc[q], lo, hi);
            float2 b = ((const float2*)sb2)[q];
            myA[2 * q]     = tanhf(lo + b.x);
            myA[2 * q + 1] = tanhf(hi + b.y);
        }

        #pragma unroll
        for (int q = 0; q < 32; q++) acc[q] = 0ull;
        matvec64(sWb, myA, acc);           // layer 3
        float H = 0.f;
        float a3[64];                      // a3 = W4*(1-t3^2) in REGISTERS
        #pragma unroll
        for (int q = 0; q < 32; q++) {
            float lo, hi; unpack2(acc[q], lo, hi);
            float2 b = ((const float2*)sb3)[q];
            float2 w4 = ((const float2*)sW4)[q];
            float t0 = tanhf(lo + b.x), t1v = tanhf(hi + b.y);
            H += w4.x * t0 + w4.y * t1v;
            a3[2 * q]     = w4.x * (1.f - t0 * t0);
            a3[2 * q + 1] = w4.y * (1.f - t1v * t1v);
        }

        // backward through W3: a2[k] = (1-t2[k]^2)*c, in place in A
        matvecT64_rolled(sWb,
            [&](int j) { return a3[j]; },
            [&](int k, float c) {
                float t2k = myA[k];
                myA[k] = c * (1.f - t2k * t2k);
            });

        // recompute t1 into registers (A now holds a2)
        float t1r[64];
        layer1_regs(sW1c, sb1, xv, t1r);

        // backward through W2: fully unrolled so t1r[k] stays static
        matvecT64_full(sWa,
            [&](int j) { return myA[j]; },
            [&](int k, float c) {
                float t1k = t1r[k];
                float cc = c * (1.f - t1k * t1k);
                ull ccd = pack2(cc, cc);
                hv = ffma2(((const ull*)sW1G)[k], ccd, hv);
                const ulonglong2* wp = (const ulonglong2*)(sW1r + k * 8);
                ulonglong2 wa = wp[0], wb = wp[1];
                gn0 = ffma2(wa.x, ccd, gn0); gn1 = ffma2(wa.y, ccd, gn1);
                gn2 = ffma2(wb.x, ccd, gn2); gn3 = ffma2(wb.y, ccd, gn3);
            });

        float h00, h01; unpack2(hv, h00, h01);
        float g0, g1, g2, g3, g4, g5, g6, g7;
        unpack2(gn0, g0, g1); unpack2(gn1, g2, g3); unpack2(gn2, g4, g5); unpack2(gn3, g6, g7);
        float fH = -(g0 * xv[0] + g1 * xv[1] + g2 * xv[2] + g3 * xv[3] +
                     g4 * xv[4] + g5 * xv[5] + g6 * xv[6] + g7 * xv[7]);
        H += Hb4[0];

        // ---- acquire lyap sibling's data (consume + reset flag) ----
        if (tid == 0) {
            while (atomicCAS(&g_flag[sub], 1, 0) != 1) { }
            __threadfence();
        }
        __syncthreads();

        float v00 = g_scr[0 * NB + elt], v01 = g_scr[1 * NB + elt];
        float fV  = g_scr[2 * NB + elt], V   = g_scr[3 * NB + elt];

        // ================= ADMM (analytic Schur) =================
        const float r    = 1.0f / 1.2f;
        const float sig  = 1e-6f;
        const float d    = 2.0f + sig;
        const float dinv = 1.0f / d;
        const float cp   = (1.0f + r * r) * (d - 1.0f) * dinv;
        const float qr = 100.f, qs = 50.f;

        float dot0 = 0.f, dot1 = 0.f;
        #pragma unroll
        for (int n = 0; n < 8; n++) {
            dot0 = fmaf(xv[n], sK[2 * n + 0], dot0);
            dot1 = fmaf(xv[n], sK[2 * n + 1], dot1);
        }
        float qu0 = 2.f * dot0, qu1 = 2.f * dot1;   // q = -2*u_nom = +2*(xK)

        float S00 = cp * (h00 * h00 + v00 * v00) + d;
        float S01 = cp * (h00 * h01 + v00 * v01);
        float S11 = cp * (h01 * h01 + v01 * v01) + d;
        float idet = 1.0f / (S00 * S11 - S01 * S01);
        float is00 = S11 * idet, is01 = -S01 * idet, is11 = S00 * idet;

        float lo0 = -(fH + H),   lo2 = -(fH * r + H);
        float hi1 = -(fV + V),   hi3 = -(fV * r + V);

        float xu0 = 0.f, xu1 = 0.f, xw0 = 0.f, xw1 = 0.f, xw2 = 0.f, xw3 = 0.f;
        float z0 = 0.f, z1 = 0.f, z2 = 0.f, z3 = 0.f, z4 = 0.f, z5 = 0.f, z6 = 0.f, z7 = 0.f;
        float y0 = 0.f, y1 = 0.f, y2 = 0.f, y3 = 0.f, y4 = 0.f, y5 = 0.f, y6 = 0.f, y7 = 0.f;

        #pragma unroll 4
        for (int it = 0; it < 80; it++) {
            float w0 = z0 - y0, w1 = z1 - y1, w2 = z2 - y2, w3 = z3 - y3;
            float w4 = z4 - y4, w5 = z5 - y5, w6 = z6 - y6, w7 = z7 - y7;
            float tA = w0 + r * w2, tB = w1 + r * w3;
            float rhsu0 = sig * xu0 - qu0 + h00 * tA + v00 * tB;
            float rhsu1 = sig * xu1 - qu1 + h01 * tA + v01 * tB;
            float rw0 = sig * xw0 - qr + (w4 - w1);
            float rw1 = sig * xw1 - qr + (w5 - w3);
            float rw2 = sig * xw2 - qs + (w6 + w0);
            float rw3 = sig * xw3 - qs + (w7 + w2);
            float e1 = rw0 + r * rw1, e2 = rw2 + r * rw3;
            float gu0 = rhsu0 - (h00 * e2 - v00 * e1) * dinv;
            float gu1 = rhsu1 - (h01 * e2 - v01 * e1) * dinv;
            xu0 = is00 * gu0 + is01 * gu1;
            xu1 = is01 * gu0 + is11 * gu1;
            float hu = h00 * xu0 + h01 * xu1;
            float vu = v00 * xu0 + v01 * xu1;
            xw0 = (rw0 + vu) * dinv;
            xw1 = (rw1 + r * vu) * dinv;
            xw2 = (rw2 - hu) * dinv;
            xw3 = (rw3 - r * hu) * dinv;
            float s0 = hu + xw2 + y0;
            float s1 = vu - xw0 + y1;
            float s2 = r * hu + xw3 + y2;
            float s3 = r * vu - xw1 + y3;
            float s4 = xw0 + y4, s5 = xw1 + y5, s6 = xw2 + y6, s7 = xw3 + y7;
            z0 = fmaxf(s0, lo0); z1 = fminf(s1, hi1);
            z2 = fmaxf(s2, lo2); z3 = fminf(s3, hi3);
            z4 = fmaxf(s4, 0.f); z5 = fmaxf(s5, 0.f);
            z6 = fmaxf(s6, 0.f); z7 = fmaxf(s7, 0.f);
            y0 = s0 - z0; y1 = s1 - z1; y2 = s2 - z2; y3 = s3 - z3;
            y4 = s4 - z4; y5 = s5 - z5; y6 = s6 - z6; y7 = s7 - z7;
        }

        // outputs: u(2NB) | relax(NB) | V | Vdot | H | Hdot
        out[2 * elt + 0] = xu0;
        out[2 * elt + 1] = xu1;
        out[2 * NB + elt] = 0.5f * (xw0 + xw1);
        out[3 * NB + elt] = V;
        out[4 * NB + elt] = (fV + v00 * xu0 + v01 * xu1) * (1.f + r) * 0.5f;
        out[5 * NB + elt] = H;
        out[6 * NB + elt] = (fH + h00 * xu0 + h01 * xu1) * (1.f + r) * 0.5f;
    }
}

extern "C" void kernel_launch(void* const* d_in, const int* in_sizes, int n_in,
                              void* d_out, int out_size) {
    const float* x   = (const float*)d_in[0];
    const float* VW1 = (const float*)d_in[1];
    const float* Vb1 = (const float*)d_in[2];
    const float* VW2 = (const float*)d_in[3];
    const float* Vb2 = (const float*)d_in[4];
    const float* HW1 = (const float*)d_in[5];
    const float* Hb1 = (const float*)d_in[6];
    const float* HW2 = (const float*)d_in[7];
    const float* Hb2 = (const float*)d_in[8];
    const float* HW3 = (const float*)d_in[9];
    const float* Hb3 = (const float*)d_in[10];
    const float* HW4 = (const float*)d_in[11];
    const float* Hb4 = (const float*)d_in[12];
    const float* G0  = (const float*)d_in[13];
    const float* K   = (const float*)d_in[14];
    float* out = (float*)d_out;

    cudaFuncSetAttribute(mlp_kernel, cudaFuncAttributeMaxDynamicSharedMemorySize, MLP_SMEM_BYTES);

    mlp_kernel<<<2 * (NB / 128), 128, MLP_SMEM_BYTES>>>(
        x, VW1, Vb1, VW2, Vb2, HW1, Hb1, HW2, Hb2, HW3, Hb3, HW4, Hb4, G0, K, out);
}

// round 13
// speedup vs baseline: 1.0580x; 1.0580x over previous
#include <cuda_runtime.h>
#include <math.h>

#define NB 32768
#define PITCH 65

typedef unsigned long long ull;

__device__ __forceinline__ ull ffma2(ull a, ull b, ull c) {
    ull d; asm("fma.rn.f32x2 %0, %1, %2, %3;" : "=l"(d) : "l"(a), "l"(b), "l"(c)); return d;
}
__device__ __forceinline__ ull pack2(float lo, float hi) {
    ull d; asm("mov.b64 %0, {%1, %2};" : "=l"(d) : "f"(lo), "f"(hi)); return d;
}
__device__ __forceinline__ void unpack2(ull v, float& lo, float& hi) {
    asm("mov.b64 {%0, %1}, %2;" : "=f"(lo), "=f"(hi) : "l"(v));
}

// scratch: [0..3]*NB = v00,v01,fV,V ; [4..7]*NB = h00,h01,fH,H
__device__ float g_scr[8 * NB];

// ---- forward 64x64 matvec: smem input; unroll 8 for LDS-latency coverage ----
__device__ __forceinline__ void matvec64(const float* __restrict__ sWc,
                                         const float* __restrict__ tin, ull acc[32]) {
    #pragma unroll 8
    for (int k = 0; k < 64; k++) {
        float tk = tin[k];
        ull td = pack2(tk, tk);
        const ulonglong2* wp = (const ulonglong2*)(sWc + (k << 6));
        #pragma unroll
        for (int q = 0; q < 16; q++) {
            ulonglong2 w = wp[q];
            acc[2 * q]     = ffma2(w.x, td, acc[2 * q]);
            acc[2 * q + 1] = ffma2(w.y, td, acc[2 * q + 1]);
        }
    }
}

// ---- transposed matvec, register-array input, kt loop rolled.
//      EPI may only use dynamic-index-safe state (smem / scalars). ----
template <typename GET, typename EPI>
__device__ __forceinline__ void matvecT64_rolled(const float* __restrict__ sWc,
                                                 GET get, EPI epi) {
    #pragma unroll 1
    for (int kt = 0; kt < 4; kt++) {
        ull cacc[16];
        #pragma unroll
        for (int i = 0; i < 16; i++) cacc[i] = 0ull;
        #pragma unroll
        for (int q = 0; q < 16; q++) {
            ull a01 = pack2(get(4 * q), get(4 * q + 1));
            ull a23 = pack2(get(4 * q + 2), get(4 * q + 3));
            #pragma unroll
            for (int i = 0; i < 16; i++) {
                const ulonglong2* wp = (const ulonglong2*)(sWc + (((kt << 4) + i) << 6));
                ulonglong2 w = wp[q];
                cacc[i] = ffma2(w.x, a01, cacc[i]);
                cacc[i] = ffma2(w.y, a23, cacc[i]);
            }
        }
        #pragma unroll
        for (int i = 0; i < 16; i++) {
            float lo, hi; unpack2(cacc[i], lo, hi);
            epi((kt << 4) + i, lo + hi);
        }
    }
}

// ---- transposed matvec, FULLY unrolled (EPI may index register arrays) ----
template <typename GET, typename EPI>
__device__ __forceinline__ void matvecT64_full(const float* __restrict__ sWc,
                                               GET get, EPI epi) {
    #pragma unroll
    for (int kt = 0; kt < 4; kt++) {
        ull cacc[16];
        #pragma unroll
        for (int i = 0; i < 16; i++) cacc[i] = 0ull;
        #pragma unroll
        for (int q = 0; q < 16; q++) {
            ull a01 = pack2(get(4 * q), get(4 * q + 1));
            ull a23 = pack2(get(4 * q + 2), get(4 * q + 3));
            #pragma unroll
            for (int i = 0; i < 16; i++) {
                const ulonglong2* wp = (const ulonglong2*)(sWc + (((kt << 4) + i) << 6));
                ulonglong2 w = wp[q];
                cacc[i] = ffma2(w.x, a01, cacc[i]);
                cacc[i] = ffma2(w.y, a23, cacc[i]);
            }
        }
        #pragma unroll
        for (int i = 0; i < 16; i++) {
            float lo, hi; unpack2(cacc[i], lo, hi);
            epi((kt << 4) + i, lo + hi);
        }
    }
}

// ---- layer 1 (8 -> 64) + tanh -> smem column ----
__device__ __forceinline__ void layer1_smem(const float* __restrict__ sW1c,
                                            const float* __restrict__ sb1,
                                            const float xv[8], float* __restrict__ out) {
    ull acc[32];
    #pragma unroll
    for (int q = 0; q < 32; q++) acc[q] = 0ull;
    #pragma unroll
    for (int n = 0; n < 8; n++) {
        ull xd = pack2(xv[n], xv[n]);
        const ulonglong2* wp = (const ulonglong2*)(sW1c + (n << 6));
        #pragma unroll
        for (int q = 0; q < 16; q++) {
            ulonglong2 w = wp[q];
            acc[2 * q]     = ffma2(w.x, xd, acc[2 * q]);
            acc[2 * q + 1] = ffma2(w.y, xd, acc[2 * q + 1]);
        }
    }
    #pragma unroll
    for (int q = 0; q < 32; q++) {
        float lo, hi; unpack2(acc[q], lo, hi);
        float2 b = ((const float2*)sb1)[q];
        out[2 * q]     = tanhf(lo + b.x);
        out[2 * q + 1] = tanhf(hi + b.y);
    }
}

// ---- layer 1 -> register array ----
__device__ __forceinline__ void layer1_regs(const float* __restrict__ sW1c,
                                            const float* __restrict__ sb1,
                                            const float xv[8], float t1r[64]) {
    ull acc[32];
    #pragma unroll
    for (int q = 0; q < 32; q++) acc[q] = 0ull;
    #pragma unroll
    for (int n = 0; n < 8; n++) {
        ull xd = pack2(xv[n], xv[n]);
        const ulonglong2* wp = (const ulonglong2*)(sW1c + (n << 6));
        #pragma unroll
        for (int q = 0; q < 16; q++) {
            ulonglong2 w = wp[q];
            acc[2 * q]     = ffma2(w.x, xd, acc[2 * q]);
            acc[2 * q + 1] = ffma2(w.y, xd, acc[2 * q + 1]);
        }
    }
    #pragma unroll
    for (int q = 0; q < 32; q++) {
        float lo, hi; unpack2(acc[q], lo, hi);
        float2 b = ((const float2*)sb1)[q];
        t1r[2 * q]     = tanhf(lo + b.x);
        t1r[2 * q + 1] = tanhf(hi + b.y);
    }
}

// ===========================================================================
// Fused MLP kernel. Heavy-first block ordering:
//   bids [0,256)   -> Barrier role (heavy)
//   bids [256,512) -> Lyapunov role (light; fills the tail wave)
// ===========================================================================
#define MLP_SMEM_FLOATS (128 * PITCH + 2 * 4096 + 512 + 512 + 128 + 4 * 64)
#define MLP_SMEM_BYTES (MLP_SMEM_FLOATS * 4)

extern "C" __global__ void __launch_bounds__(128, 3) mlp_kernel(
    const float* __restrict__ x,
    const float* __restrict__ VW1, const float* __restrict__ Vb1,
    const float* __restrict__ VW2, const float* __restrict__ Vb2,
    const float* __restrict__ HW1, const float* __restrict__ Hb1,
    const float* __restrict__ HW2, const float* __restrict__ Hb2,
    const float* __restrict__ HW3, const float* __restrict__ Hb3,
    const float* __restrict__ HW4, const float* __restrict__ Hb4,
    const float* __restrict__ G0)
{
    extern __shared__ float sm[];
    float* scrA = sm;                      // 128*PITCH (one column / element)
    float* sWa  = scrA + 128 * PITCH;      // 4096: W2 col-major [k][j]
    float* sWb  = sWa + 4096;              // 4096: W3 col-major (barrier only)
    float* sW1c = sWb + 4096;              // 512  [n][j]
    float* sW1r = sW1c + 512;              // 512  row-major
    float* sW1G = sW1r + 512;              // 128  [k] pairs (g0,g1)
    float* sb1  = sW1G + 128;              // 64
    float* sb2  = sb1 + 64;                // 64
    float* sb3  = sb2 + 64;                // 64
    float* sW4  = sb3 + 64;                // 64

    const int tid  = threadIdx.x;
    const int role = (blockIdx.x < 256) ? 1 : 0;   // heavy barrier blocks first
    const int sub  = blockIdx.x & 255;

    const float* W1 = role ? HW1 : VW1;
    const float* B1 = role ? Hb1 : Vb1;
    const float* W2 = role ? HW2 : VW2;
    const float* B2 = role ? Hb2 : Vb2;

    for (int i = tid; i < 4096; i += 128) {
        int j = i >> 6, k = i & 63;
        sWa[k * 64 + j] = W2[i];
        if (role) sWb[k * 64 + j] = HW3[i];
    }
    for (int i = tid; i < 512; i += 128) {
        int j = i >> 3, n = i & 7;
        sW1c[n * 64 + j] = W1[i];
        sW1r[i] = W1[i];
    }
    if (tid < 64) {
        sb1[tid] = B1[tid]; sb2[tid] = B2[tid];
        if (role) { sb3[tid] = Hb3[tid]; sW4[tid] = HW4[tid]; }
        float g0 = 0.f, g1 = 0.f;
        for (int n = 0; n < 8; n++) {
            float w = W1[tid * 8 + n];
            g0 = fmaf(w, G0[2 * n], g0);
            g1 = fmaf(w, G0[2 * n + 1], g1);
        }
        sW1G[2 * tid] = g0; sW1G[2 * tid + 1] = g1;
    }
    __syncthreads();

    const int elt = sub * 128 + tid;
    float4 xlo = ((const float4*)x)[elt * 2];
    float4 xhi = ((const float4*)x)[elt * 2 + 1];
    float xv[8] = {xlo.x, xlo.y, xlo.z, xlo.w, xhi.x, xhi.y, xhi.z, xhi.w};
    float* myA = scrA + tid * PITCH;

    // scalar accumulators for the final backward-through-W1 contraction
    ull hv = 0ull, gn0 = 0ull, gn1 = 0ull, gn2 = 0ull, gn3 = 0ull;

    if (role == 0) {
        // ================= Lyapunov =================
        layer1_smem(sW1c, sb1, xv, myA);   // t1 -> A (persists)

        ull acc[32];
        #pragma unroll
        for (int q = 0; q < 32; q++) acc[q] = 0ull;
        matvec64(sWa, myA, acc);           // layer-2 pre-activation

        float V = 0.f;
        float a2[64];                      // a2 = t2*(1-t2^2) in REGISTERS
        #pragma unroll
        for (int q = 0; q < 32; q++) {
            float lo, hi; unpack2(acc[q], lo, hi);
            float2 b = ((const float2*)sb2)[q];
            float t0 = tanhf(lo + b.x), t1v = tanhf(hi + b.y);
            V += t0 * t0 + t1v * t1v;
            a2[2 * q]     = t0 * (1.f - t0 * t0);
            a2[2 * q + 1] = t1v * (1.f - t1v * t1v);
        }
        V *= 0.5f;

        // backward through W2: epi reads t1 from smem (dynamic k safe)
        matvecT64_rolled(sWa,
            [&](int j) { return a2[j]; },
            [&](int k, float c) {
                float t1k = myA[k];
                float cc = c * (1.f - t1k * t1k);
                ull ccd = pack2(cc, cc);
                hv = ffma2(((const ull*)sW1G)[k], ccd, hv);
                const ulonglong2* wp = (const ulonglong2*)(sW1r + k * 8);
                ulonglong2 wa = wp[0], wb = wp[1];
                gn0 = ffma2(wa.x, ccd, gn0); gn1 = ffma2(wa.y, ccd, gn1);
                gn2 = ffma2(wb.x, ccd, gn2); gn3 = ffma2(wb.y, ccd, gn3);
            });

        float p0, p1; unpack2(hv, p0, p1);
        float g0, g1, g2, g3, g4, g5, g6, g7;
        unpack2(gn0, g0, g1); unpack2(gn1, g2, g3); unpack2(gn2, g4, g5); unpack2(gn3, g6, g7);
        float fV = -(g0 * xv[0] + g1 * xv[1] + g2 * xv[2] + g3 * xv[3] +
                     g4 * xv[4] + g5 * xv[5] + g6 * xv[6] + g7 * xv[7]);
        g_scr[0 * NB + elt] = p0;
        g_scr[1 * NB + elt] = p1;
        g_scr[2 * NB + elt] = fV;
        g_scr[3 * NB + elt] = V;
    } else {
        // ================= Barrier =================
        layer1_smem(sW1c, sb1, xv, myA);   // t1 -> A (temporary)

        ull acc[32];
        #pragma unroll
        for (int q = 0; q < 32; q++) acc[q] = 0ull;
        matvec64(sWa, myA, acc);           // layer 2 (consumes all of t1)
        #pragma unroll
        for (int q = 0; q < 32; q++) {     // t2 overwrites A
            float lo, hi; unpack2(acc[q], lo, hi);
            float2 b = ((const float2*)sb2)[q];
            myA[2 * q]     = tanhf(lo + b.x);
            myA[2 * q + 1] = tanhf(hi + b.y);
        }

        #pragma unroll
        for (int q = 0; q < 32; q++) acc[q] = 0ull;
        matvec64(sWb, myA, acc);           // layer 3
        float H = 0.f;
        float a3[64];                      // a3 = W4*(1-t3^2) in REGISTERS
        #pragma unroll
        for (int q = 0; q < 32; q++) {
            float lo, hi; unpack2(acc[q], lo, hi);
            float2 b = ((const float2*)sb3)[q];
            float2 w4 = ((const float2*)sW4)[q];
            float t0 = tanhf(lo + b.x), t1v = tanhf(hi + b.y);
            H += w4.x * t0 + w4.y * t1v;
            a3[2 * q]     = w4.x * (1.f - t0 * t0);
            a3[2 * q + 1] = w4.y * (1.f - t1v * t1v);
        }

        // backward through W3: a2[k] = (1-t2[k]^2)*c, in place in A
        matvecT64_rolled(sWb,
            [&](int j) { return a3[j]; },
            [&](int k, float c) {
                float t2k = myA[k];
                myA[k] = c * (1.f - t2k * t2k);
            });

        // recompute t1 into registers (A now holds a2)
        float t1r[64];
        layer1_regs(sW1c, sb1, xv, t1r);

        // backward through W2: fully unrolled so t1r[k] stays static
        matvecT64_full(sWa,
            [&](int j) { return myA[j]; },
            [&](int k, float c) {
                float t1k = t1r[k];
                float cc = c * (1.f - t1k * t1k);
                ull ccd = pack2(cc, cc);
                hv = ffma2(((const ull*)sW1G)[k], ccd, hv);
                const ulonglong2* wp = (const ulonglong2*)(sW1r + k * 8);
                ulonglong2 wa = wp[0], wb = wp[1];
                gn0 = ffma2(wa.x, ccd, gn0); gn1 = ffma2(wa.y, ccd, gn1);
                gn2 = ffma2(wb.x, ccd, gn2); gn3 = ffma2(wb.y, ccd, gn3);
            });

        float p0, p1; unpack2(hv, p0, p1);
        float g0, g1, g2, g3, g4, g5, g6, g7;
        unpack2(gn0, g0, g1); unpack2(gn1, g2, g3); unpack2(gn2, g4, g5); unpack2(gn3, g6, g7);
        float fH = -(g0 * xv[0] + g1 * xv[1] + g2 * xv[2] + g3 * xv[3] +
                     g4 * xv[4] + g5 * xv[5] + g6 * xv[6] + g7 * xv[7]);
        g_scr[4 * NB + elt] = p0;
        g_scr[5 * NB + elt] = p1;
        g_scr[6 * NB + elt] = fH;
        g_scr[7 * NB + elt] = H + Hb4[0];
    }
}

// ===========================================================================
// ADMM kernel: 1 thread / element, analytic block inverse of M (Schur form)
// ===========================================================================
__global__ void __launch_bounds__(128) admm_kernel(
    const float* __restrict__ x, const float* __restrict__ K,
    float* __restrict__ out)
{
    __shared__ float sK[16];
    if (threadIdx.x < 16) sK[threadIdx.x] = K[threadIdx.x];
    __syncthreads();

    int i = blockIdx.x * 128 + threadIdx.x;

    float v00 = g_scr[0 * NB + i], v01 = g_scr[1 * NB + i];
    float fV  = g_scr[2 * NB + i], V   = g_scr[3 * NB + i];
    float h00 = g_scr[4 * NB + i], h01 = g_scr[5 * NB + i];
    float fH  = g_scr[6 * NB + i], H   = g_scr[7 * NB + i];

    const float4* xp = (const float4*)(x + (size_t)i * 8);
    float4 xa = xp[0], xb = xp[1];
    float xv[8] = {xa.x, xa.y, xa.z, xa.w, xb.x, xb.y, xb.z, xb.w};
    float un0 = 0.f, un1 = 0.f;
    #pragma unroll
    for (int n = 0; n < 8; n++) {
        un0 = fmaf(xv[n], sK[2 * n + 0], un0);
        un1 = fmaf(xv[n], sK[2 * n + 1], un1);
    }
    un0 = -un0; un1 = -un1;   // u_nom (M_NOM = 1)

    const float r    = 1.0f / 1.2f;
    const float sig  = 1e-6f;
    const float d    = 2.0f + sig;
    const float dinv = 1.0f / d;
    const float cfac = 1.0f + r * r;
    const float cp   = cfac * (d - 1.0f) * dinv;

    float S00 = cp * (h00 * h00 + v00 * v00) + d;
    float S01 = cp * (h00 * h01 + v00 * v01);
    float S11 = cp * (h01 * h01 + v01 * v01) + d;
    float idet = 1.0f / (S00 * S11 - S01 * S01);
    float is00 = S11 * idet, is01 = -S01 * idet, is11 = S00 * idet;

    float qu0 = -2.f * un0, qu1 = -2.f * un1;
    const float qr = 100.f, qs = 50.f;
    float lo0 = -(fH + H),     lo2 = -(fH * r + H);
    float hi1 = -(fV + V),     hi3 = -(fV * r + V);

    float xu0 = 0.f, xu1 = 0.f, xw0 = 0.f, xw1 = 0.f, xw2 = 0.f, xw3 = 0.f;
    float z0 = 0.f, z1 = 0.f, z2 = 0.f, z3 = 0.f, z4 = 0.f, z5 = 0.f, z6 = 0.f, z7 = 0.f;
    float y0 = 0.f, y1 = 0.f, y2 = 0.f, y3 = 0.f, y4 = 0.f, y5 = 0.f, y6 = 0.f, y7 = 0.f;

    #pragma unroll 4
    for (int it = 0; it < 80; it++) {
        float w0 = z0 - y0, w1 = z1 - y1, w2 = z2 - y2, w3 = z3 - y3;
        float w4 = z4 - y4, w5 = z5 - y5, w6 = z6 - y6, w7 = z7 - y7;
        float tA = w0 + r * w2, tB = w1 + r * w3;
        float rhsu0 = sig * xu0 - qu0 + h00 * tA + v00 * tB;
        float rhsu1 = sig * xu1 - qu1 + h01 * tA + v01 * tB;
        float rw0 = sig * xw0 - qr + (w4 - w1);
        float rw1 = sig * xw1 - qr + (w5 - w3);
        float rw2 = sig * xw2 - qs + (w6 + w0);
        float rw3 = sig * xw3 - qs + (w7 + w2);
        float e1 = rw0 + r * rw1, e2 = rw2 + r * rw3;
        float gu0 = rhsu0 - (h00 * e2 - v00 * e1) * dinv;
        float gu1 = rhsu1 - (h01 * e2 - v01 * e1) * dinv;
        xu0 = is00 * gu0 + is01 * gu1;
        xu1 = is01 * gu0 + is11 * gu1;
        float hu = h00 * xu0 + h01 * xu1;
        float vu = v00 * xu0 + v01 * xu1;
        xw0 = (rw0 + vu) * dinv;
        xw1 = (rw1 + r * vu) * dinv;
        xw2 = (rw2 - hu) * dinv;
        xw3 = (rw3 - r * hu) * dinv;
        float s0 = hu + xw2 + y0;
        float s1 = vu - xw0 + y1;
        float s2 = r * hu + xw3 + y2;
        float s3 = r * vu - xw1 + y3;
        float s4 = xw0 + y4, s5 = xw1 + y5, s6 = xw2 + y6, s7 = xw3 + y7;
        z0 = fmaxf(s0, lo0); z1 = fminf(s1, hi1);
        z2 = fmaxf(s2, lo2); z3 = fminf(s3, hi3);
        z4 = fmaxf(s4, 0.f); z5 = fmaxf(s5, 0.f);
        z6 = fmaxf(s6, 0.f); z7 = fmaxf(s7, 0.f);
        y0 = s0 - z0; y1 = s1 - z1; y2 = s2 - z2; y3 = s3 - z3;
        y4 = s4 - z4; y5 = s5 - z5; y6 = s6 - z6; y7 = s7 - z7;
    }

    out[2 * i + 0] = xu0;
    out[2 * i + 1] = xu1;
    out[2 * NB + i] = 0.5f * (xw0 + xw1);
    out[3 * NB + i] = V;
    out[4 * NB + i] = (fV + v00 * xu0 + v01 * xu1) * (1.f + r) * 0.5f;
    out[5 * NB + i] = H;
    out[6 * NB + i] = (fH + h00 * xu0 + h01 * xu1) * (1.f + r) * 0.5f;
}

extern "C" void kernel_launch(void* const* d_in, const int* in_sizes, int n_in,
                              void* d_out, int out_size) {
    const float* x   = (const float*)d_in[0];
    const float* VW1 = (const float*)d_in[1];
    const float* Vb1 = (const float*)d_in[2];
    const float* VW2 = (const float*)d_in[3];
    const float* Vb2 = (const float*)d_in[4];
    const float* HW1 = (const float*)d_in[5];
    const float* Hb1 = (const float*)d_in[6];
    const float* HW2 = (const float*)d_in[7];
    const float* Hb2 = (const float*)d_in[8];
    const float* HW3 = (const float*)d_in[9];
    const float* Hb3 = (const float*)d_in[10];
    const float* HW4 = (const float*)d_in[11];
    const float* Hb4 = (const float*)d_in[12];
    const float* G0  = (const float*)d_in[13];
    const float* K   = (const float*)d_in[14];
    float* out = (float*)d_out;

    cudaFuncSetAttribute(mlp_kernel, cudaFuncAttributeMaxDynamicSharedMemorySize, MLP_SMEM_BYTES);

    mlp_kernel<<<2 * (NB / 128), 128, MLP_SMEM_BYTES>>>(
        x, VW1, Vb1, VW2, Vb2, HW1, Hb1, HW2, Hb2, HW3, Hb3, HW4, Hb4, G0);
    admm_kernel<<<NB / 128, 128>>>(x, K, out);
}